// round 3
// baseline (speedup 1.0000x reference)
#include <cuda_runtime.h>
#include <cuda_bf16.h>
#include <math.h>

#define Hdim 1024
#define Ldim 10
#define Vdim 50257
#define NBLK 148
#define NTHR 1024
#define CHUNK ((Vdim + NBLK - 1) / NBLK)   // 340

// ---- persistent scratch (no allocations allowed) ----
__device__ __align__(16) float g_scores[Ldim];
__device__ __align__(16) float g_x[Hdim];
__device__ __align__(16) float g_hnew[Hdim];
__device__ __align__(16) float g_logits[Vdim];
__device__ float g_pmax[NBLK];
__device__ float g_psum[NBLK];
__device__ unsigned g_bar_count = 0;
__device__ volatile unsigned g_bar_sense = 0;
__device__ unsigned g_tile = 0;

__device__ __forceinline__ float warp_sum(float s) {
#pragma unroll
    for (int o = 16; o; o >>= 1) s += __shfl_down_sync(0xffffffffu, s, o);
    return s;
}

// online logsumexp merge: (m,s) <- merge((m,s),(m2,s2))
__device__ __forceinline__ void lse_merge(float& m, float& s, float m2, float s2) {
    if (m2 > m) { s = s * expf(m - m2) + s2; m = m2; }
    else if (s2 > 0.f) { s += s2 * expf(m2 - m); }
}

// sense-reversing software grid barrier (all 148 blocks co-resident)
__device__ __forceinline__ void grid_barrier(unsigned* s_sense) {
    __syncthreads();
    if (threadIdx.x == 0) {
        unsigned ns = *s_sense ^ 1u;
        *s_sense = ns;
        __threadfence();
        if (atomicAdd(&g_bar_count, 1u) == (unsigned)(gridDim.x - 1)) {
            g_bar_count = 0;
            __threadfence();
            g_bar_sense = ns;
        } else {
            while (g_bar_sense != ns) { }
        }
        __threadfence();
    }
    __syncthreads();
}

__global__ __launch_bounds__(NTHR, 1)
void fused_decoder(const int* __restrict__ inp,
                   const float* __restrict__ hidden,
                   const float* __restrict__ enc,
                   const float* __restrict__ emb,
                   const float* __restrict__ attn_W,
                   const float* __restrict__ attn_b,
                   const float* __restrict__ comb_W,
                   const float* __restrict__ comb_b,
                   const float* __restrict__ wih,
                   const float* __restrict__ whh,
                   const float* __restrict__ bih,
                   const float* __restrict__ bhh,
                   const float* __restrict__ outW,
                   const float* __restrict__ outb,
                   float* __restrict__ out, int out_size) {
    __shared__ __align__(16) float s_buf[2 * Hdim];   // xcat / h
    __shared__ float s_red[32];
    __shared__ float s_redm[32], s_reds[32];
    __shared__ unsigned s_sense;
    __shared__ float s_shift;

    int tid = threadIdx.x, bid = blockIdx.x;
    int warp = tid >> 5, lane = tid & 31;

    if (tid == 0) {
        s_sense = g_bar_sense;         // stable between launches
        if (bid == 0) g_tile = 0;      // reset work-steal counter
    }

    int tok = inp[0];
    const float* erow = emb + (size_t)tok * Hdim;

    // ---------------- Phase 1: attention scores (blocks 0..9) ----------------
    if (bid < Ldim) {
        const float* wrow = attn_W + (size_t)bid * 2 * Hdim;
        float s = wrow[tid] * erow[tid] + wrow[Hdim + tid] * hidden[tid];
        s = warp_sum(s);
        if (lane == 0) s_red[warp] = s;
        __syncthreads();
        if (warp == 0) {
            float v = s_red[lane];
            v = warp_sum(v);
            if (lane == 0) g_scores[bid] = v + attn_b[bid];
        }
    }
    grid_barrier(&s_sense);

    // ---------------- Phase 2: softmax + xcat (redundant per block) ----------
    {
        float w[Ldim];
        float m = g_scores[0];
#pragma unroll
        for (int l = 1; l < Ldim; l++) m = fmaxf(m, g_scores[l]);
        float ssum = 0.f;
#pragma unroll
        for (int l = 0; l < Ldim; l++) { w[l] = expf(g_scores[l] - m); ssum += w[l]; }
        float inv = 1.f / ssum;
#pragma unroll
        for (int l = 0; l < Ldim; l++) w[l] *= inv;

        if (bid == 0 && tid < Ldim && out_size >= Vdim + Hdim + Ldim)
            out[Vdim + Hdim + tid] = w[tid];

        float a = 0.f;
#pragma unroll
        for (int l = 0; l < Ldim; l++) a += w[l] * enc[l * Hdim + tid];
        s_buf[tid] = erow[tid];
        s_buf[Hdim + tid] = a;
    }
    __syncthreads();

    // ---------------- Phase 3: comb = relu(comb_W @ xcat + b) ----------------
    {
        int r = warp * NBLK + bid;                 // rows interleaved across blocks
        if (r < Hdim) {
            const float4* wr = (const float4*)(comb_W + (size_t)r * 2 * Hdim);
            const float4* xc = (const float4*)s_buf;
            float s = 0.f;
#pragma unroll 8
            for (int k = 0; k < 16; k++) {
                int idx = lane + 32 * k;
                float4 a = __ldcs(wr + idx);
                float4 x = xc[idx];
                s += a.x * x.x + a.y * x.y + a.z * x.z + a.w * x.w;
            }
            s = warp_sum(s);
            if (lane == 0) g_x[r] = fmaxf(s + comb_b[r], 0.f);
        }
    }
    grid_barrier(&s_sense);

    // ---------------- Phase 4: GRU step ----------------
    {
        int u = warp * NBLK + bid;
        if (u < Hdim) {
            const float4* x4 = (const float4*)g_x;
            const float4* h4 = (const float4*)hidden;
            const float4* wir = (const float4*)(wih + (size_t)u * Hdim);
            const float4* wiz = (const float4*)(wih + (size_t)(u + Hdim) * Hdim);
            const float4* win = (const float4*)(wih + (size_t)(u + 2 * Hdim) * Hdim);
            const float4* whr = (const float4*)(whh + (size_t)u * Hdim);
            const float4* whz = (const float4*)(whh + (size_t)(u + Hdim) * Hdim);
            const float4* whn = (const float4*)(whh + (size_t)(u + 2 * Hdim) * Hdim);
            float s0 = 0, s1 = 0, s2 = 0, s3 = 0, s4 = 0, s5 = 0;
#pragma unroll
            for (int k = 0; k < 8; k++) {
                int idx = lane + 32 * k;
                float4 xv = x4[idx], hv = h4[idx];
                float4 a;
                a = __ldcs(wir + idx); s0 += a.x * xv.x + a.y * xv.y + a.z * xv.z + a.w * xv.w;
                a = __ldcs(wiz + idx); s1 += a.x * xv.x + a.y * xv.y + a.z * xv.z + a.w * xv.w;
                a = __ldcs(win + idx); s2 += a.x * xv.x + a.y * xv.y + a.z * xv.z + a.w * xv.w;
                a = __ldcs(whr + idx); s3 += a.x * hv.x + a.y * hv.y + a.z * hv.z + a.w * hv.w;
                a = __ldcs(whz + idx); s4 += a.x * hv.x + a.y * hv.y + a.z * hv.z + a.w * hv.w;
                a = __ldcs(whn + idx); s5 += a.x * hv.x + a.y * hv.y + a.z * hv.z + a.w * hv.w;
            }
            s0 = warp_sum(s0); s1 = warp_sum(s1); s2 = warp_sum(s2);
            s3 = warp_sum(s3); s4 = warp_sum(s4); s5 = warp_sum(s5);
            if (lane == 0) {
                float r = 1.f / (1.f + expf(-((s0 + bih[u]) + (s3 + bhh[u]))));
                float z = 1.f / (1.f + expf(-((s1 + bih[Hdim + u]) + (s4 + bhh[Hdim + u]))));
                float n = tanhf((s2 + bih[2 * Hdim + u]) + r * (s5 + bhh[2 * Hdim + u]));
                float hn = (1.f - z) * n + z * hidden[u];
                g_hnew[u] = hn;
                if (out_size >= Vdim + Hdim) out[Vdim + u] = hn;
            }
        }
    }
    grid_barrier(&s_sense);

    // ---------------- Phase 5: logits + per-block (max,sumexp), work stealing -
    s_buf[tid] = g_hnew[tid & (Hdim - 1)];
    __syncthreads();
    {
        const float4* hh = (const float4*)s_buf;
        float m = -INFINITY, ssum = 0.f;
        int t;
        if (lane == 0) t = atomicAdd(&g_tile, 1u);
        t = __shfl_sync(0xffffffffu, t, 0);
        while (2 * t < Vdim) {
            int tn;
            if (lane == 0) tn = atomicAdd(&g_tile, 1u);   // prefetch next tile
            int r0 = 2 * t, r1 = r0 + 1;
            bool v1 = r1 < Vdim;
            const float4* w0 = (const float4*)(outW + (size_t)r0 * Hdim);
            const float4* w1 = (const float4*)(outW + (size_t)(v1 ? r1 : r0) * Hdim);
            float a0 = 0.f, a1 = 0.f;
#pragma unroll
            for (int k = 0; k < 8; k++) {
                int idx = lane + 32 * k;
                float4 h = hh[idx];
                float4 wa = __ldcs(w0 + idx);
                float4 wb = __ldcs(w1 + idx);
                a0 += wa.x * h.x + wa.y * h.y + wa.z * h.z + wa.w * h.w;
                a1 += wb.x * h.x + wb.y * h.y + wb.z * h.z + wb.w * h.w;
            }
            a0 = warp_sum(a0);
            a1 = warp_sum(a1);
            if (lane == 0) {
                float lg0 = a0 + outb[r0];
                g_logits[r0] = lg0;
                lse_merge(m, ssum, lg0, 1.f);
                if (v1) {
                    float lg1 = a1 + outb[r1];
                    g_logits[r1] = lg1;
                    lse_merge(m, ssum, lg1, 1.f);
                }
            }
            tn = __shfl_sync(0xffffffffu, tn, 0);
            t = tn;
        }
        if (lane == 0) { s_redm[warp] = m; s_reds[warp] = ssum; }
    }
    __syncthreads();
    if (tid == 0) {
        float m = -INFINITY, s = 0.f;
#pragma unroll
        for (int w = 0; w < 32; w++) lse_merge(m, s, s_redm[w], s_reds[w]);
        g_pmax[bid] = m;
        g_psum[bid] = s;
    }
    grid_barrier(&s_sense);

    // ---------------- Phase 6: global logsumexp + write ----------------
    if (warp == 0) {
        float m = -INFINITY, s = 0.f;
        for (int i = lane; i < NBLK; i += 32) lse_merge(m, s, g_pmax[i], g_psum[i]);
#pragma unroll
        for (int off = 16; off; off >>= 1) {
            float m2 = __shfl_xor_sync(0xffffffffu, m, off);
            float s2 = __shfl_xor_sync(0xffffffffu, s, off);
            lse_merge(m, s, m2, s2);
        }
        if (lane == 0) s_shift = m + logf(s);
    }
    __syncthreads();
    {
        int v0 = bid * CHUNK;
        for (int v = v0 + tid; v < v0 + CHUNK && v < Vdim; v += NTHR)
            out[v] = g_logits[v] - s_shift;
    }
}

extern "C" void kernel_launch(void* const* d_in, const int* in_sizes, int n_in,
                              void* d_out, int out_size) {
    const int*   inp    = (const int*)  d_in[0];
    const float* hidden = (const float*)d_in[1];
    const float* enc    = (const float*)d_in[2];
    const float* emb    = (const float*)d_in[3];
    const float* attn_W = (const float*)d_in[4];
    const float* attn_b = (const float*)d_in[5];
    const float* comb_W = (const float*)d_in[6];
    const float* comb_b = (const float*)d_in[7];
    const float* gruwih = (const float*)d_in[8];
    const float* gruwhh = (const float*)d_in[9];
    const float* grubih = (const float*)d_in[10];
    const float* grubhh = (const float*)d_in[11];
    const float* out_W  = (const float*)d_in[12];
    const float* out_b  = (const float*)d_in[13];
    float* out = (float*)d_out;

    fused_decoder<<<NBLK, NTHR>>>(inp, hidden, enc, emb, attn_W, attn_b,
                                  comb_W, comb_b, gruwih, gruwhh, grubih, grubhh,
                                  out_W, out_b, out, out_size);
}

// round 4
// speedup vs baseline: 1.2036x; 1.2036x over previous
#include <cuda_runtime.h>
#include <cuda_bf16.h>
#include <math.h>

#define Hdim 1024
#define Ldim 10
#define Vdim 50257
#define ROWS_PER_BLK 32                                   // k5: 16 warps x 2 rows
#define NB5 ((Vdim + ROWS_PER_BLK - 1) / ROWS_PER_BLK)    // 1571
#define NB7 ((Vdim + 255) / 256)                          // 197

// ---- scratch (no allocations allowed) ----
__device__ __align__(16) float g_xcat[2 * Hdim];   // [embedded, attn_applied]
__device__ __align__(16) float g_x[Hdim];          // relu(comb)
__device__ __align__(16) float g_hnew[Hdim];       // GRU output
__device__ __align__(16) float g_logits[Vdim];
__device__ float g_pmax[NB5];
__device__ float g_psum[NB5];

__device__ __forceinline__ float warp_sum(float s) {
#pragma unroll
    for (int o = 16; o; o >>= 1) s += __shfl_down_sync(0xffffffffu, s, o);
    return s;
}

// K1: embedding gather + attention scores + softmax + attn_applied -> g_xcat
__global__ void k1_attn(const int* __restrict__ inp,
                        const float* __restrict__ hidden,
                        const float* __restrict__ enc,
                        const float* __restrict__ emb,
                        const float* __restrict__ attn_W,
                        const float* __restrict__ attn_b,
                        float* __restrict__ out, int out_size) {
    cudaTriggerProgrammaticLaunchCompletion();
    __shared__ float sw[Ldim];
    int tid = threadIdx.x;
    int warp = tid >> 5, lane = tid & 31;
    int tok = inp[0];
    const float* erow = emb + (size_t)tok * Hdim;

    if (warp < Ldim) {
        const float* wrow = attn_W + (size_t)warp * 2 * Hdim;
        float s = 0.f;
        for (int j = lane; j < Hdim; j += 32)
            s += wrow[j] * erow[j] + wrow[Hdim + j] * hidden[j];
        s = warp_sum(s);
        if (lane == 0) sw[warp] = s + attn_b[warp];
    }
    __syncthreads();
    if (tid == 0) {
        float m = sw[0];
#pragma unroll
        for (int l = 1; l < Ldim; l++) m = fmaxf(m, sw[l]);
        float e[Ldim], ssum = 0.f;
#pragma unroll
        for (int l = 0; l < Ldim; l++) { e[l] = expf(sw[l] - m); ssum += e[l]; }
#pragma unroll
        for (int l = 0; l < Ldim; l++) sw[l] = e[l] / ssum;
    }
    __syncthreads();
    if (tid < Ldim && out_size >= Vdim + Hdim + Ldim)
        out[Vdim + Hdim + tid] = sw[tid];
    int j = tid;
    if (j < Hdim) {
        float a = 0.f;
#pragma unroll
        for (int l = 0; l < Ldim; l++) a += sw[l] * enc[l * Hdim + j];
        g_xcat[j] = erow[j];
        g_xcat[Hdim + j] = a;
    }
}

// K2: g_x[row] = relu(comb_W[row,:] . g_xcat + b).  Block per row, 512 threads.
// Weight loads issued BEFORE gridsync (independent of k1) — stream under k1.
__global__ __launch_bounds__(512) void k2_comb(const float* __restrict__ comb_W,
                                               const float* __restrict__ comb_b) {
    cudaTriggerProgrammaticLaunchCompletion();
    __shared__ float red[16];
    int row = blockIdx.x;
    int tid = threadIdx.x, warp = tid >> 5, lane = tid & 31;
    const float4* wr = (const float4*)(comb_W + (size_t)row * 2 * Hdim);
    float4 w = __ldcs(wr + tid);
    float bias = (tid == 0) ? comb_b[row] : 0.f;
    cudaGridDependencySynchronize();
    float4 x = ((const float4*)g_xcat)[tid];
    float s = w.x * x.x + w.y * x.y + w.z * x.z + w.w * x.w;
    s = warp_sum(s);
    if (lane == 0) red[warp] = s;
    __syncthreads();
    if (warp == 0) {
        float v = (lane < 16) ? red[lane] : 0.f;
        v = warp_sum(v);
        if (lane == 0) g_x[row] = fmaxf(v + bias, 0.f);
    }
}

// K3: GRU step. Block per hidden unit; all 6 weight rows prefetched pre-gridsync.
__global__ __launch_bounds__(256) void k3_gru(const float* __restrict__ hidden,
                                              const float* __restrict__ wih,
                                              const float* __restrict__ whh,
                                              const float* __restrict__ bih,
                                              const float* __restrict__ bhh,
                                              float* __restrict__ out, int out_size) {
    cudaTriggerProgrammaticLaunchCompletion();
    __shared__ float red[6][8];
    int u = blockIdx.x;
    int tid = threadIdx.x, warp = tid >> 5, lane = tid & 31;
    const float4* wir = (const float4*)(wih + (size_t)u * Hdim);
    const float4* wiz = (const float4*)(wih + (size_t)(u + Hdim) * Hdim);
    const float4* win = (const float4*)(wih + (size_t)(u + 2 * Hdim) * Hdim);
    const float4* whr = (const float4*)(whh + (size_t)u * Hdim);
    const float4* whz = (const float4*)(whh + (size_t)(u + Hdim) * Hdim);
    const float4* whn = (const float4*)(whh + (size_t)(u + 2 * Hdim) * Hdim);
    // independent loads: weights + previous hidden state
    float4 a0 = __ldcs(wir + tid);
    float4 a1 = __ldcs(wiz + tid);
    float4 a2 = __ldcs(win + tid);
    float4 a3 = __ldcs(whr + tid);
    float4 a4 = __ldcs(whz + tid);
    float4 a5 = __ldcs(whn + tid);
    float4 hv = ((const float4*)hidden)[tid];
    cudaGridDependencySynchronize();
    float4 xv = ((const float4*)g_x)[tid];
    float s0 = a0.x * xv.x + a0.y * xv.y + a0.z * xv.z + a0.w * xv.w;
    float s1 = a1.x * xv.x + a1.y * xv.y + a1.z * xv.z + a1.w * xv.w;
    float s2 = a2.x * xv.x + a2.y * xv.y + a2.z * xv.z + a2.w * xv.w;
    float s3 = a3.x * hv.x + a3.y * hv.y + a3.z * hv.z + a3.w * hv.w;
    float s4 = a4.x * hv.x + a4.y * hv.y + a4.z * hv.z + a4.w * hv.w;
    float s5 = a5.x * hv.x + a5.y * hv.y + a5.z * hv.z + a5.w * hv.w;
    s0 = warp_sum(s0); s1 = warp_sum(s1); s2 = warp_sum(s2);
    s3 = warp_sum(s3); s4 = warp_sum(s4); s5 = warp_sum(s5);
    if (lane == 0) {
        red[0][warp] = s0; red[1][warp] = s1; red[2][warp] = s2;
        red[3][warp] = s3; red[4][warp] = s4; red[5][warp] = s5;
    }
    __syncthreads();
    if (tid == 0) {
        float g[6];
#pragma unroll
        for (int gi = 0; gi < 6; gi++) {
            float acc = 0.f;
#pragma unroll
            for (int w = 0; w < 8; w++) acc += red[gi][w];
            g[gi] = acc;
        }
        float r = 1.f / (1.f + expf(-((g[0] + bih[u]) + (g[3] + bhh[u]))));
        float z = 1.f / (1.f + expf(-((g[1] + bih[Hdim + u]) + (g[4] + bhh[Hdim + u]))));
        float n = tanhf((g[2] + bih[2 * Hdim + u]) + r * (g[5] + bhh[2 * Hdim + u]));
        float hn = (1.f - z) * n + z * hidden[u];
        g_hnew[u] = hn;
        if (out_size >= Vdim + Hdim) out[Vdim + u] = hn;
    }
}

// K5: logits + per-block (max, sumexp). 512 threads, 16 warps x 2 rows.
// First weight tile prefetched pre-gridsync.
__global__ __launch_bounds__(512) void k5_logits(const float* __restrict__ outW,
                                                 const float* __restrict__ outb) {
    cudaTriggerProgrammaticLaunchCompletion();
    __shared__ __align__(16) float sh[Hdim];
    __shared__ float slog[ROWS_PER_BLK];
    int tid = threadIdx.x, warp = tid >> 5, lane = tid & 31;
    int row0 = blockIdx.x * ROWS_PER_BLK + warp * 2;
    int row1 = row0 + 1;
    bool v0 = row0 < Vdim, v1 = row1 < Vdim;
    const float4* wr0 = (const float4*)(outW + (size_t)(v0 ? row0 : 0) * Hdim);
    const float4* wr1 = (const float4*)(outW + (size_t)(v1 ? row1 : 0) * Hdim);
    // prefetch k=0 tile while waiting on GRU
    float4 p0 = __ldcs(wr0 + lane);
    float4 p1 = __ldcs(wr1 + lane);
    cudaGridDependencySynchronize();
    sh[tid] = g_hnew[tid];
    sh[tid + 512] = g_hnew[tid + 512];
    __syncthreads();
    const float4* hh = (const float4*)sh;
    float4 h0 = hh[lane];
    float s0 = p0.x * h0.x + p0.y * h0.y + p0.z * h0.z + p0.w * h0.w;
    float s1 = p1.x * h0.x + p1.y * h0.y + p1.z * h0.z + p1.w * h0.w;
#pragma unroll
    for (int k = 1; k < 8; k++) {
        int idx = lane + 32 * k;
        float4 h = hh[idx];
        float4 w0 = __ldcs(wr0 + idx);
        float4 w1 = __ldcs(wr1 + idx);
        s0 += w0.x * h.x + w0.y * h.y + w0.z * h.z + w0.w * h.w;
        s1 += w1.x * h.x + w1.y * h.y + w1.z * h.z + w1.w * h.w;
    }
    s0 = warp_sum(s0);
    s1 = warp_sum(s1);
    if (lane == 0) {
        float lg0 = v0 ? (s0 + outb[row0]) : -INFINITY;
        float lg1 = v1 ? (s1 + outb[row1]) : -INFINITY;
        if (v0) g_logits[row0] = lg0;
        if (v1) g_logits[row1] = lg1;
        slog[warp * 2] = lg0;
        slog[warp * 2 + 1] = lg1;
    }
    __syncthreads();
    if (tid == 0) {
        float m = slog[0];
#pragma unroll
        for (int w = 1; w < ROWS_PER_BLK; w++) m = fmaxf(m, slog[w]);
        float s = 0.f;
#pragma unroll
        for (int w = 0; w < ROWS_PER_BLK; w++) s += expf(slog[w] - m);
        g_pmax[blockIdx.x] = m;
        g_psum[blockIdx.x] = s;
    }
}

// K67: fused global logsumexp reduce (redundant per block) + output write.
__global__ __launch_bounds__(256) void k67_write(float* __restrict__ out) {
    cudaGridDependencySynchronize();
    __shared__ float sm[256], ss[256];
    int tid = threadIdx.x;
    float m = -INFINITY, s = 0.f;
    for (int b = tid; b < NB5; b += 256) {
        float bm = g_pmax[b], bs = g_psum[b];
        if (bm > m) { s = s * expf(m - bm) + bs; m = bm; }
        else        { s += bs * expf(bm - m); }
    }
    sm[tid] = m; ss[tid] = s;
    __syncthreads();
#pragma unroll
    for (int o = 128; o; o >>= 1) {
        if (tid < o) {
            float m2 = sm[tid + o], s2 = ss[tid + o];
            if (m2 > sm[tid]) { ss[tid] = ss[tid] * expf(sm[tid] - m2) + s2; sm[tid] = m2; }
            else              { ss[tid] += s2 * expf(m2 - sm[tid]); }
        }
        __syncthreads();
    }
    __shared__ float shift;
    if (tid == 0) shift = sm[0] + logf(ss[0]);
    __syncthreads();
    int v = blockIdx.x * 256 + tid;
    if (v < Vdim) out[v] = g_logits[v] - shift;
}

static inline void launch_pdl(void* func, dim3 grid, dim3 block,
                              void** args) {
    cudaLaunchAttribute attr[1];
    attr[0].id = cudaLaunchAttributeProgrammaticStreamSerialization;
    attr[0].val.programmaticStreamSerializationAllowed = 1;
    cudaLaunchConfig_t cfg = {};
    cfg.gridDim = grid;
    cfg.blockDim = block;
    cfg.dynamicSmemBytes = 0;
    cfg.stream = 0;
    cfg.attrs = attr;
    cfg.numAttrs = 1;
    cudaLaunchKernelExC(&cfg, func, args);
}

extern "C" void kernel_launch(void* const* d_in, const int* in_sizes, int n_in,
                              void* d_out, int out_size) {
    const int*   inp    = (const int*)  d_in[0];
    const float* hidden = (const float*)d_in[1];
    const float* enc    = (const float*)d_in[2];
    const float* emb    = (const float*)d_in[3];
    const float* attn_W = (const float*)d_in[4];
    const float* attn_b = (const float*)d_in[5];
    const float* comb_W = (const float*)d_in[6];
    const float* comb_b = (const float*)d_in[7];
    const float* gruwih = (const float*)d_in[8];
    const float* gruwhh = (const float*)d_in[9];
    const float* grubih = (const float*)d_in[10];
    const float* grubhh = (const float*)d_in[11];
    const float* out_W  = (const float*)d_in[12];
    const float* out_b  = (const float*)d_in[13];
    float* out = (float*)d_out;

    k1_attn<<<1, 1024>>>(inp, hidden, enc, emb, attn_W, attn_b, out, out_size);

    {
        void* args[] = { (void*)&comb_W, (void*)&comb_b };
        launch_pdl((void*)k2_comb, dim3(Hdim), dim3(512), args);
    }
    {
        void* args[] = { (void*)&hidden, (void*)&gruwih, (void*)&gruwhh,
                         (void*)&grubih, (void*)&grubhh, (void*)&out, (void*)&out_size };
        launch_pdl((void*)k3_gru, dim3(Hdim), dim3(256), args);
    }
    {
        void* args[] = { (void*)&out_W, (void*)&out_b };
        launch_pdl((void*)k5_logits, dim3(NB5), dim3(512), args);
    }
    {
        void* args[] = { (void*)&out };
        launch_pdl((void*)k67_write, dim3(NB7), dim3(256), args);
    }
}

// round 5
// speedup vs baseline: 1.2766x; 1.0606x over previous
#include <cuda_runtime.h>
#include <cuda_bf16.h>
#include <math.h>

#define Hdim 1024
#define Ldim 10
#define Vdim 50257
#define NWARP5 16
#define MAXNB5 512
#define NB7 ((Vdim + 255) / 256)                          // 197

// ---- scratch (no allocations allowed) ----
__device__ __align__(16) float g_xcat[2 * Hdim];   // [embedded, attn_applied]
__device__ __align__(16) float g_x[Hdim];          // relu(comb)
__device__ __align__(16) float g_hnew[Hdim];       // GRU output
__device__ __align__(16) float g_logits[Vdim];
__device__ float g_pmax[MAXNB5];
__device__ float g_psum[MAXNB5];

__device__ __forceinline__ float warp_sum(float s) {
#pragma unroll
    for (int o = 16; o; o >>= 1) s += __shfl_down_sync(0xffffffffu, s, o);
    return s;
}

__device__ __forceinline__ void lse_merge(float& m, float& s, float m2, float s2) {
    if (m2 > m) { s = s * expf(m - m2) + s2; m = m2; }
    else if (s2 > 0.f) { s += s2 * expf(m2 - m); }
}

__device__ __forceinline__ void l2_prefetch(const void* p) {
    asm volatile("prefetch.global.L2 [%0];" :: "l"(p));
}

// K1: embedding gather + attention scores + softmax + attn_applied -> g_xcat
__global__ void k1_attn(const int* __restrict__ inp,
                        const float* __restrict__ hidden,
                        const float* __restrict__ enc,
                        const float* __restrict__ emb,
                        const float* __restrict__ attn_W,
                        const float* __restrict__ attn_b,
                        float* __restrict__ out, int out_size) {
    cudaTriggerProgrammaticLaunchCompletion();
    __shared__ float sw[Ldim];
    int tid = threadIdx.x;
    int warp = tid >> 5, lane = tid & 31;
    int tok = inp[0];
    const float* erow = emb + (size_t)tok * Hdim;

    if (warp < Ldim) {
        const float* wrow = attn_W + (size_t)warp * 2 * Hdim;
        float s = 0.f;
        for (int j = lane; j < Hdim; j += 32)
            s += wrow[j] * erow[j] + wrow[Hdim + j] * hidden[j];
        s = warp_sum(s);
        if (lane == 0) sw[warp] = s + attn_b[warp];
    }
    __syncthreads();
    if (tid == 0) {
        float m = sw[0];
#pragma unroll
        for (int l = 1; l < Ldim; l++) m = fmaxf(m, sw[l]);
        float e[Ldim], ssum = 0.f;
#pragma unroll
        for (int l = 0; l < Ldim; l++) { e[l] = expf(sw[l] - m); ssum += e[l]; }
#pragma unroll
        for (int l = 0; l < Ldim; l++) sw[l] = e[l] / ssum;
    }
    __syncthreads();
    if (tid < Ldim && out_size >= Vdim + Hdim + Ldim)
        out[Vdim + Hdim + tid] = sw[tid];
    int j = tid;
    if (j < Hdim) {
        float a = 0.f;
#pragma unroll
        for (int l = 0; l < Ldim; l++) a += sw[l] * enc[l * Hdim + j];
        g_xcat[j] = erow[j];
        g_xcat[Hdim + j] = a;
    }
}

// K2: g_x[row] = relu(comb_W[row,:] . g_xcat + b).  Block per row, 512 threads.
__global__ __launch_bounds__(512) void k2_comb(const float* __restrict__ comb_W,
                                               const float* __restrict__ comb_b) {
    cudaTriggerProgrammaticLaunchCompletion();
    __shared__ float red[16];
    int row = blockIdx.x;
    int tid = threadIdx.x, warp = tid >> 5, lane = tid & 31;
    const float4* wr = (const float4*)(comb_W + (size_t)row * 2 * Hdim);
    float4 w = __ldcs(wr + tid);
    float bias = (tid == 0) ? comb_b[row] : 0.f;
    cudaGridDependencySynchronize();
    float4 x = ((const float4*)g_xcat)[tid];
    float s = w.x * x.x + w.y * x.y + w.z * x.z + w.w * x.w;
    s = warp_sum(s);
    if (lane == 0) red[warp] = s;
    __syncthreads();
    if (warp == 0) {
        float v = (lane < 16) ? red[lane] : 0.f;
        v = warp_sum(v);
        if (lane == 0) g_x[row] = fmaxf(v + bias, 0.f);
    }
}

// K3: GRU step. Block per hidden unit; all 6 weight rows prefetched pre-gridsync.
__global__ __launch_bounds__(256) void k3_gru(const float* __restrict__ hidden,
                                              const float* __restrict__ wih,
                                              const float* __restrict__ whh,
                                              const float* __restrict__ bih,
                                              const float* __restrict__ bhh,
                                              float* __restrict__ out, int out_size) {
    cudaTriggerProgrammaticLaunchCompletion();
    __shared__ float red[6][8];
    int u = blockIdx.x;
    int tid = threadIdx.x, warp = tid >> 5, lane = tid & 31;
    const float4* wir = (const float4*)(wih + (size_t)u * Hdim);
    const float4* wiz = (const float4*)(wih + (size_t)(u + Hdim) * Hdim);
    const float4* win = (const float4*)(wih + (size_t)(u + 2 * Hdim) * Hdim);
    const float4* whr = (const float4*)(whh + (size_t)u * Hdim);
    const float4* whz = (const float4*)(whh + (size_t)(u + Hdim) * Hdim);
    const float4* whn = (const float4*)(whh + (size_t)(u + 2 * Hdim) * Hdim);
    float4 a0 = __ldcs(wir + tid);
    float4 a1 = __ldcs(wiz + tid);
    float4 a2 = __ldcs(win + tid);
    float4 a3 = __ldcs(whr + tid);
    float4 a4 = __ldcs(whz + tid);
    float4 a5 = __ldcs(whn + tid);
    float4 hv = ((const float4*)hidden)[tid];
    cudaGridDependencySynchronize();
    float4 xv = ((const float4*)g_x)[tid];
    float s0 = a0.x * xv.x + a0.y * xv.y + a0.z * xv.z + a0.w * xv.w;
    float s1 = a1.x * xv.x + a1.y * xv.y + a1.z * xv.z + a1.w * xv.w;
    float s2 = a2.x * xv.x + a2.y * xv.y + a2.z * xv.z + a2.w * xv.w;
    float s3 = a3.x * hv.x + a3.y * hv.y + a3.z * hv.z + a3.w * hv.w;
    float s4 = a4.x * hv.x + a4.y * hv.y + a4.z * hv.z + a4.w * hv.w;
    float s5 = a5.x * hv.x + a5.y * hv.y + a5.z * hv.z + a5.w * hv.w;
    s0 = warp_sum(s0); s1 = warp_sum(s1); s2 = warp_sum(s2);
    s3 = warp_sum(s3); s4 = warp_sum(s4); s5 = warp_sum(s5);
    if (lane == 0) {
        red[0][warp] = s0; red[1][warp] = s1; red[2][warp] = s2;
        red[3][warp] = s3; red[4][warp] = s4; red[5][warp] = s5;
    }
    __syncthreads();
    if (tid == 0) {
        float g[6];
#pragma unroll
        for (int gi = 0; gi < 6; gi++) {
            float acc = 0.f;
#pragma unroll
            for (int w = 0; w < 8; w++) acc += red[gi][w];
            g[gi] = acc;
        }
        float r = 1.f / (1.f + expf(-((g[0] + bih[u]) + (g[3] + bhh[u]))));
        float z = 1.f / (1.f + expf(-((g[1] + bih[Hdim + u]) + (g[4] + bhh[Hdim + u]))));
        float n = tanhf((g[2] + bih[2 * Hdim + u]) + r * (g[5] + bhh[2 * Hdim + u]));
        float hn = (1.f - z) * n + z * hidden[u];
        g_hnew[u] = hn;
        if (out_size >= Vdim + Hdim) out[Vdim + u] = hn;
    }
}

// K5: PERSISTENT logits + per-block (max,sumexp). One wave: grid = 2*SMs.
// Each block owns a contiguous row chunk; warps interleave, 2 rows/iter.
__global__ __launch_bounds__(512, 2) void k5_logits(const float* __restrict__ outW,
                                                    const float* __restrict__ outb) {
    __shared__ __align__(16) float sh[Hdim];
    __shared__ float sm[NWARP5], ss[NWARP5];
    int tid = threadIdx.x, warp = tid >> 5, lane = tid & 31;

    int per = (Vdim + gridDim.x - 1) / gridDim.x;
    int start = blockIdx.x * per;
    int end = start + per; if (end > Vdim) end = Vdim;

    // warm L2 with this warp's first two rows while GRU runs
    {
        int r0 = start + 2 * warp;
        if (r0 < end) {
            l2_prefetch((const char*)(outW + (size_t)r0 * Hdim) + lane * 128);
            if (r0 + 1 < end)
                l2_prefetch((const char*)(outW + (size_t)(r0 + 1) * Hdim) + lane * 128);
        }
    }
    cudaTriggerProgrammaticLaunchCompletion();
    cudaGridDependencySynchronize();

    sh[tid] = g_hnew[tid];
    sh[tid + 512] = g_hnew[tid + 512];
    __syncthreads();
    const float4* hh = (const float4*)sh;

    float m = -INFINITY, ssum = 0.f;
    for (int r = start + 2 * warp; r < end; r += 2 * NWARP5) {
        int r1 = r + 1;
        bool v1 = r1 < end;
        const float4* w0 = (const float4*)(outW + (size_t)r * Hdim);
        const float4* w1 = (const float4*)(outW + (size_t)(v1 ? r1 : r) * Hdim);
        float a0 = 0.f, a1 = 0.f;
#pragma unroll
        for (int k = 0; k < 8; k++) {
            int idx = lane + 32 * k;
            float4 h = hh[idx];
            float4 wa = __ldcs(w0 + idx);
            float4 wb = __ldcs(w1 + idx);
            a0 += wa.x * h.x + wa.y * h.y + wa.z * h.z + wa.w * h.w;
            a1 += wb.x * h.x + wb.y * h.y + wb.z * h.z + wb.w * h.w;
        }
        a0 = warp_sum(a0);
        a1 = warp_sum(a1);
        if (lane == 0) {
            float lg0 = a0 + outb[r];
            g_logits[r] = lg0;
            lse_merge(m, ssum, lg0, 1.f);
            if (v1) {
                float lg1 = a1 + outb[r1];
                g_logits[r1] = lg1;
                lse_merge(m, ssum, lg1, 1.f);
            }
        }
    }
    if (lane == 0) { sm[warp] = m; ss[warp] = ssum; }
    __syncthreads();
    if (tid == 0) {
        float gm = -INFINITY, gs = 0.f;
#pragma unroll
        for (int w = 0; w < NWARP5; w++) lse_merge(gm, gs, sm[w], ss[w]);
        g_pmax[blockIdx.x] = gm;
        g_psum[blockIdx.x] = gs;
    }
}

// K67: fused global logsumexp reduce (redundant per block) + output write.
__global__ __launch_bounds__(256) void k67_write(float* __restrict__ out, int nb5) {
    cudaGridDependencySynchronize();
    __shared__ float sm[256], ss[256];
    int tid = threadIdx.x;
    float m = -INFINITY, s = 0.f;
    for (int b = tid; b < nb5; b += 256)
        lse_merge(m, s, g_pmax[b], g_psum[b]);
    sm[tid] = m; ss[tid] = s;
    __syncthreads();
#pragma unroll
    for (int o = 128; o; o >>= 1) {
        if (tid < o) {
            lse_merge(sm[tid], ss[tid], sm[tid + o], ss[tid + o]);
        }
        __syncthreads();
    }
    __shared__ float shift;
    if (tid == 0) shift = sm[0] + logf(ss[0]);
    __syncthreads();
    int v = blockIdx.x * 256 + tid;
    if (v < Vdim) out[v] = g_logits[v] - shift;
}

static inline void launch_pdl(void* func, dim3 grid, dim3 block, void** args) {
    cudaLaunchAttribute attr[1];
    attr[0].id = cudaLaunchAttributeProgrammaticStreamSerialization;
    attr[0].val.programmaticStreamSerializationAllowed = 1;
    cudaLaunchConfig_t cfg = {};
    cfg.gridDim = grid;
    cfg.blockDim = block;
    cfg.dynamicSmemBytes = 0;
    cfg.stream = 0;
    cfg.attrs = attr;
    cfg.numAttrs = 1;
    cudaLaunchKernelExC(&cfg, func, args);
}

extern "C" void kernel_launch(void* const* d_in, const int* in_sizes, int n_in,
                              void* d_out, int out_size) {
    const int*   inp    = (const int*)  d_in[0];
    const float* hidden = (const float*)d_in[1];
    const float* enc    = (const float*)d_in[2];
    const float* emb    = (const float*)d_in[3];
    const float* attn_W = (const float*)d_in[4];
    const float* attn_b = (const float*)d_in[5];
    const float* comb_W = (const float*)d_in[6];
    const float* comb_b = (const float*)d_in[7];
    const float* gruwih = (const float*)d_in[8];
    const float* gruwhh = (const float*)d_in[9];
    const float* grubih = (const float*)d_in[10];
    const float* grubhh = (const float*)d_in[11];
    const float* out_W  = (const float*)d_in[12];
    const float* out_b  = (const float*)d_in[13];
    float* out = (float*)d_out;

    int dev = 0, nsm = 148;
    cudaGetDevice(&dev);
    cudaDeviceGetAttribute(&nsm, cudaDevAttrMultiProcessorCount, dev);
    int nb5 = 2 * nsm;
    if (nb5 > MAXNB5) nb5 = MAXNB5;

    k1_attn<<<1, 1024>>>(inp, hidden, enc, emb, attn_W, attn_b, out, out_size);

    {
        void* args[] = { (void*)&comb_W, (void*)&comb_b };
        launch_pdl((void*)k2_comb, dim3(Hdim), dim3(512), args);
    }
    {
        void* args[] = { (void*)&hidden, (void*)&gruwih, (void*)&gruwhh,
                         (void*)&grubih, (void*)&grubhh, (void*)&out, (void*)&out_size };
        launch_pdl((void*)k3_gru, dim3(Hdim), dim3(256), args);
    }
    {
        void* args[] = { (void*)&out_W, (void*)&out_b };
        launch_pdl((void*)k5_logits, dim3(nb5), dim3(512), args);
    }
    {
        void* args[] = { (void*)&out, (void*)&nb5 };
        launch_pdl((void*)k67_write, dim3(NB7), dim3(256), args);
    }
}